// round 11
// baseline (speedup 1.0000x reference)
#include <cuda_runtime.h>
#include <cstdint>

// compressor_17454747091102: bitwise majority vote (>=5 of 8) over packed sign bits.
// out bit set iff >=5 of 8 voters have the bit set (vote sum < 0).
// Bit-sliced carry-save adder -> threshold c8 | (c4 & (c2 | c1)).
// Output buffer dtype is float32 (round-1 evidence): store float32((int32)word).
//
// Evidence so far:
//  R4: 1024 blk, MLP8  -> ncu 10.0us / harness 9.7  (2-wave tail)
//  R8: 512 blk,  MLP8  -> ncu 9.0us  / harness 6.69 (3-vs-4 blocks/SM, 15% spread)
//  R9: 256 blk,  MLP16 -> ncu 9.2us  / harness 7.62 (1-vs-2 blocks/SM, 27% spread)
// Cold (ncu) dur is invariant ~9us => DRAM-side ceiling ~4.2TB/s; the scored
// harness replay is L2-warm (37.7MB << 126MB L2) and is bound by per-SM work
// balance. R10: 592 = 148*4 blocks, even 4/SM single wave, each block owns a
// contiguous 442-443-tile chunk (0.2% max spread), simple loop body (regs~40).

__device__ __forceinline__ void full_add(uint32_t a, uint32_t b, uint32_t c,
                                         uint32_t& s, uint32_t& cy) {
    uint32_t ab = a ^ b;
    s  = ab ^ c;
    cy = (a & b) | (c & ab);
}

__device__ __forceinline__ uint32_t maj5of8(const uint32_t w[8]) {
    uint32_t s_a, c_a, s_b, c_b, s_c, c_c;
    full_add(w[0], w[1], w[2], s_a, c_a);
    full_add(w[3], w[4], w[5], s_b, c_b);
    full_add(w[6], w[7], s_a, s_c, c_c);
    uint32_t s_d = s_b ^ s_c;          // c1
    uint32_t c_d = s_b & s_c;
    uint32_t s_e, c_e;
    full_add(c_a, c_b, c_c, s_e, c_e);
    uint32_t s_f = s_e ^ c_d;          // c2
    uint32_t c_f = s_e & c_d;
    uint32_t s_g = c_e ^ c_f;          // c4
    uint32_t c_g = c_e & c_f;          // c8
    return c_g | (s_g & (s_f | s_d)); // count >= 5
}

__global__ void __launch_bounds__(256)
compressor_17454747091102_kernel(const uint4* __restrict__ src,
                                 float4* __restrict__ out,
                                 int m4, int base, int rem) {
    // Block b owns contiguous tile range [start, end):
    //   blocks [0, rem) get base+1 tiles, the rest get base.
    int b = blockIdx.x;
    int start = b * base + (b < rem ? b : rem);
    int end   = start + base + (b < rem ? 1 : 0);

    for (int idx = start + threadIdx.x; idx < end; idx += blockDim.x) {
        uint4 v[8];
#pragma unroll
        for (int t = 0; t < 8; t++)
            v[t] = src[(size_t)t * m4 + idx];

        uint32_t wx[8], wy[8], wz[8], ww[8];
#pragma unroll
        for (int t = 0; t < 8; t++) {
            wx[t] = v[t].x; wy[t] = v[t].y; wz[t] = v[t].z; ww[t] = v[t].w;
        }

        float4 r;
        r.x = (float)(int)maj5of8(wx);
        r.y = (float)(int)maj5of8(wy);
        r.z = (float)(int)maj5of8(wz);
        r.w = (float)(int)maj5of8(ww);
        out[idx] = r;
    }
}

extern "C" void kernel_launch(void* const* d_in, const int* in_sizes, int n_in,
                              void* d_out, int out_size) {
    // d_in[0] = para_temp (float, unused), d_in[1] = src_tensor_list (int32, 8*M)
    const uint4* src = (const uint4*)d_in[1];
    float4* out = (float4*)d_out;
    int M  = in_sizes[1] / 8;    // packed words per voter (2^20)
    int m4 = M / 4;              // uint4 tiles per voter (262144)

    const int blocks  = 148 * 4; // 592: even 4 blocks/SM, single wave
    const int threads = 256;
    int base = m4 / blocks;      // 442
    int rem  = m4 - base * blocks; // 480 blocks carry one extra tile
    compressor_17454747091102_kernel<<<blocks, threads>>>(src, out, m4, base, rem);
}